// round 10
// baseline (speedup 1.0000x reference)
#include <cuda_runtime.h>
#include <math.h>

#define BB 128
#define SS 512
#define HH 1024

// ---------------- scratch (device globals: no allocation allowed) ----------
__device__ float g_XB[(size_t)BB * SS * HH];     // x @ Bm^T
__device__ float g_G [(size_t)BB * SS * HH];     // sigmoid(x @ Wg^T + bg)
__device__ float g_Sbuf[(size_t)BB * SS * HH];   // all states s_t, (b, t, h)
__device__ float g_sT[2][HH][BB];                // k-major state, ping-pong
__device__ unsigned g_count;                     // grid barrier counter
__device__ unsigned g_gen;                       // grid barrier generation

// ---------------- software grid barrier (all CTAs resident) ----------------
__device__ __forceinline__ void gsync(unsigned nblk, unsigned& gen) {
    __syncthreads();
    gen += 1;
    if (threadIdx.x == 0) {
        __threadfence();                               // release my writes
        if (atomicAdd(&g_count, 1u) == nblk - 1u) {
            atomicExch(&g_count, 0u);
            __threadfence();
            atomicExch(&g_gen, gen);
        } else {
            while (*(volatile unsigned*)&g_gen != gen) { }
            __threadfence();                           // acquire
        }
    }
    __syncthreads();
}

// ---------------- SGEMM: out[m,n] = sum_k X[m,k] * W[n,k] ------------------
// Eigen-style kc=512 blocking: result = add(chain(k=0..511), chain(k=512..1023)),
// each chain a single k-ascending FMA accumulator.
// EPI==1: sigmoid(acc + bias[n]) via 1/(1+expf(-x)).
template <int EPI>
__global__ __launch_bounds__(256) void sgemm_nt(
    const float* __restrict__ X, const float* __restrict__ W,
    const float* __restrict__ bias, float* __restrict__ out,
    int M, int N, int K)
{
    __shared__ float Xs[16][132];   // transposed stage, padded
    __shared__ float Ws[16][68];

    const int n0 = blockIdx.x * 64;     // n fastest -> X tile reused via L2
    const int m0 = blockIdx.y * 128;
    const int tid = threadIdx.x;
    const int tx = tid & 15;            // 16 col-groups of 4
    const int ty = tid >> 4;            // 16 row-groups of 8

    float acc[8][4];                    // current kc-panel accumulator
    float accL[8][4];                   // saved low-panel (k < 512) result
#pragma unroll
    for (int i = 0; i < 8; i++)
#pragma unroll
        for (int j = 0; j < 4; j++) { acc[i][j] = 0.f; accL[i][j] = 0.f; }

    for (int k0 = 0; k0 < K; k0 += 16) {
#pragma unroll
        for (int l = 0; l < 2; l++) {
            int idx = tid + l * 256;          // 512 float4 loads: 128 rows x 4 quads
            int row = idx >> 2;
            int kq  = (idx & 3) * 4;
            const float4 v = *reinterpret_cast<const float4*>(
                X + (size_t)(m0 + row) * K + k0 + kq);
            Xs[kq + 0][row] = v.x; Xs[kq + 1][row] = v.y;
            Xs[kq + 2][row] = v.z; Xs[kq + 3][row] = v.w;
        }
        {
            int row = tid >> 2;               // 64 rows x 4 quads = 256 threads
            int kq  = (tid & 3) * 4;
            const float4 v = *reinterpret_cast<const float4*>(
                W + (size_t)(n0 + row) * K + k0 + kq);
            Ws[kq + 0][row] = v.x; Ws[kq + 1][row] = v.y;
            Ws[kq + 2][row] = v.z; Ws[kq + 3][row] = v.w;
        }
        __syncthreads();
#pragma unroll
        for (int k = 0; k < 16; k++) {        // k strictly ascending
            float a[8], b[4];
            *reinterpret_cast<float4*>(&a[0]) = *reinterpret_cast<const float4*>(&Xs[k][ty * 8]);
            *reinterpret_cast<float4*>(&a[4]) = *reinterpret_cast<const float4*>(&Xs[k][ty * 8 + 4]);
            *reinterpret_cast<float4*>(&b[0]) = *reinterpret_cast<const float4*>(&Ws[k][tx * 4]);
#pragma unroll
            for (int i = 0; i < 8; i++)
#pragma unroll
                for (int j = 0; j < 4; j++)
                    acc[i][j] = fmaf(a[i], b[j], acc[i][j]);
        }
        __syncthreads();

        // kc=512 panel boundary: save low-half chain, restart accumulator
        if (k0 + 16 == 512) {
#pragma unroll
            for (int i = 0; i < 8; i++)
#pragma unroll
                for (int j = 0; j < 4; j++) { accL[i][j] = acc[i][j]; acc[i][j] = 0.f; }
        }
    }

    float bv[4];
    if (EPI == 1) {
#pragma unroll
        for (int j = 0; j < 4; j++) bv[j] = bias[n0 + tx * 4 + j];
    }
#pragma unroll
    for (int i = 0; i < 8; i++) {
        float vals[4];
#pragma unroll
        for (int j = 0; j < 4; j++) {
            float v = __fadd_rn(accL[i][j], acc[i][j]);   // add(chain_lo, chain_hi)
            if (EPI == 1) v = 1.f / (1.f + expf(-(v + bv[j])));
            vals[j] = v;
        }
        float4 o; o.x = vals[0]; o.y = vals[1]; o.z = vals[2]; o.w = vals[3];
        *reinterpret_cast<float4*>(out + (size_t)(m0 + ty * 8 + i) * N + n0 + tx * 4) = o;
    }
}

// ---------------- persistent scan kernel (r1 structure, unchanged) ---------
// grid = 128 CTAs x 256 threads. CTA owns 8 output channels h0..h0+7.
// thread: m = tid&127 (batch row), half = tid>>7 (k-split: 512 k each).
// dotA = add(chain(k<512), chain(k>=512)) — matches the GEMM blocking.
__global__ __launch_bounds__(256) void scan_kernel(
    const float* __restrict__ state0, const float* __restrict__ A,
    const float* __restrict__ log_dt,
    const float* __restrict__ XB, const float* __restrict__ G,
    float* __restrict__ Sbuf, float* __restrict__ out_state)
{
    __shared__ float As[HH][8];      // A slice: As[k][j] = A[h0+j][k]
    __shared__ float Rs[BB][9];      // half-1 partial sums (pad 9)

    const int tid  = threadIdx.x;
    const int h0   = blockIdx.x * 8;
    const int m    = tid & 127;
    const int half = tid >> 7;
    const int kbase = half * 512;
    const unsigned nblk = gridDim.x;

    for (int idx = tid; idx < 8 * HH; idx += 256) {
        int j = idx >> 10, k = idx & 1023;
        As[k][j] = A[(size_t)(h0 + j) * HH + k];
    }
    if (tid < BB) {
#pragma unroll
        for (int j = 0; j < 8; j++)
            g_sT[0][h0 + j][tid] = state0[(size_t)tid * HH + h0 + j];
    }

    float dt[8], sreg[8];
    if (half == 0) {
#pragma unroll
        for (int j = 0; j < 8; j++) {
            float d = expf(log_dt[h0 + j]);
            dt[j] = fminf(fmaxf(d, 0.001f), 0.1f);
            sreg[j] = state0[(size_t)m * HH + h0 + j];
        }
    }

    unsigned gen = *(volatile unsigned*)&g_gen;
    gsync(nblk, gen);

    const float* sbase = &g_sT[0][0][0];

    for (int t = 0; t < SS; t++) {
        const int cur = t & 1;
        const int nxt = cur ^ 1;

        float4 xb0, xb1, gg0, gg1;
        size_t rowbase = ((size_t)m * SS + t) * HH + h0;
        if (half == 0) {
            xb0 = *reinterpret_cast<const float4*>(XB + rowbase);
            xb1 = *reinterpret_cast<const float4*>(XB + rowbase + 4);
            gg0 = *reinterpret_cast<const float4*>(G + rowbase);
            gg1 = *reinterpret_cast<const float4*>(G + rowbase + 4);
        }

        // single k-ascending chain over this thread's 512-k half
        float acc[8];
#pragma unroll
        for (int j = 0; j < 8; j++) acc[j] = 0.f;

        const float* sp = sbase + (size_t)cur * HH * BB + (size_t)kbase * BB + m;
#pragma unroll 1
        for (int kk = 0; kk < 512; kk += 8) {
            float sv[8];
#pragma unroll
            for (int u = 0; u < 8; u++)
                sv[u] = __ldcg(sp + (size_t)(kk + u) * BB);
#pragma unroll
            for (int u = 0; u < 8; u++) {
                const float4 a0 = *reinterpret_cast<const float4*>(&As[kbase + kk + u][0]);
                const float4 a1 = *reinterpret_cast<const float4*>(&As[kbase + kk + u][4]);
                acc[0] = fmaf(sv[u], a0.x, acc[0]);
                acc[1] = fmaf(sv[u], a0.y, acc[1]);
                acc[2] = fmaf(sv[u], a0.z, acc[2]);
                acc[3] = fmaf(sv[u], a0.w, acc[3]);
                acc[4] = fmaf(sv[u], a1.x, acc[4]);
                acc[5] = fmaf(sv[u], a1.y, acc[5]);
                acc[6] = fmaf(sv[u], a1.z, acc[6]);
                acc[7] = fmaf(sv[u], a1.w, acc[7]);
            }
        }

        if (half == 1) {
#pragma unroll
            for (int j = 0; j < 8; j++) Rs[m][j] = acc[j];
        }
        __syncthreads();

        if (half == 0) {
            float xb[8] = {xb0.x, xb0.y, xb0.z, xb0.w, xb1.x, xb1.y, xb1.z, xb1.w};
            float gv[8] = {gg0.x, gg0.y, gg0.z, gg0.w, gg1.x, gg1.y, gg1.z, gg1.w};
            float sn[8];
#pragma unroll
            for (int j = 0; j < 8; j++) {
                float dstate = acc[j] + Rs[m][j] + xb[j];   // (lo+hi)+xb
                float sc = dstate * dt[j];
                if (fabsf(sc) <= 0.1f) sc = 0.f;
                float v = sreg[j] + sc * gv[j];             // default contraction (as r1)
                sreg[j] = v;
                sn[j] = v;
                g_sT[nxt][h0 + j][m] = v;
            }
            float4 o0; o0.x = sn[0]; o0.y = sn[1]; o0.z = sn[2]; o0.w = sn[3];
            float4 o1; o1.x = sn[4]; o1.y = sn[5]; o1.z = sn[6]; o1.w = sn[7];
            *reinterpret_cast<float4*>(Sbuf + rowbase)     = o0;
            *reinterpret_cast<float4*>(Sbuf + rowbase + 4) = o1;
            if (t == SS - 1 && out_state != nullptr) {
#pragma unroll
                for (int j = 0; j < 8; j++)
                    out_state[(size_t)m * HH + h0 + j] = sn[j];
            }
        }

        gsync(nblk, gen);
    }
}

// ---------------- launch ----------------------------------------------------
extern "C" void kernel_launch(void* const* d_in, const int* in_sizes, int n_in,
                              void* d_out, int out_size) {
    const float* x      = (const float*)d_in[0];
    const float* state  = (const float*)d_in[1];
    const float* A      = (const float*)d_in[2];
    const float* Bm     = (const float*)d_in[3];
    const float* C      = (const float*)d_in[4];
    const float* log_dt = (const float*)d_in[5];
    const float* Wg     = (const float*)d_in[6];
    const float* bg     = (const float*)d_in[7];

    float* ys = (float*)d_out;
    const size_t ys_elems = (size_t)BB * SS * HH;
    float* out_state = nullptr;
    if ((size_t)out_size >= ys_elems + (size_t)BB * HH)
        out_state = ys + ys_elems;

    float *pXB = nullptr, *pG = nullptr, *pS = nullptr;
    cudaGetSymbolAddress((void**)&pXB, g_XB);
    cudaGetSymbolAddress((void**)&pG,  g_G);
    cudaGetSymbolAddress((void**)&pS,  g_Sbuf);

    const int M = BB * SS;           // 65536
    dim3 grid(HH / 64, M / 128);     // (16, 512), n fastest

    // off-critical-path GEMMs (kc=512 blocked chains)
    sgemm_nt<0><<<grid, 256>>>(x, Bm, nullptr, pXB, M, HH, HH);
    sgemm_nt<1><<<grid, 256>>>(x, Wg, bg,      pG,  M, HH, HH);

    // sequential scan (persistent, 128 CTAs), 2x512 chains
    scan_kernel<<<BB, 256>>>(state, A, log_dt, pXB, pG, pS, out_state);

    // y = Sbuf @ C^T (kc=512 blocked chains)
    sgemm_nt<0><<<grid, 256>>>(pS, C, nullptr, ys, M, HH, HH);
}

// round 11
// speedup vs baseline: 1.1041x; 1.1041x over previous
#include <cuda_runtime.h>
#include <math.h>

#define BB 128
#define SS 512
#define HH 1024

// ---------------- scratch (device globals: no allocation allowed) ----------
__device__ float g_XB[(size_t)BB * SS * HH];     // x @ Bm^T
__device__ float g_G [(size_t)BB * SS * HH];     // sigmoid(x @ Wg^T + bg)
__device__ float g_Sbuf[(size_t)BB * SS * HH];   // all states s_t, (b, t, h)
__device__ float g_sT[2][HH][BB];                // k-major state, ping-pong
__device__ unsigned g_cnt[8 * 32];               // group arrival counters (padded lines)
__device__ unsigned g_master;                    // group-completion counter
__device__ unsigned g_gen;                       // published generation

// ---------------- two-level grid barrier (128 CTAs resident) ---------------
// Cumulative counters (no reset) -> graph-replay safe. 8 groups of 16 CTAs.
__device__ __forceinline__ void gsync(int bid, unsigned& gen) {
    __syncthreads();
    gen += 1;
    if (threadIdx.x == 0) {
        __threadfence();                                   // release my writes
        unsigned r = atomicAdd(&g_cnt[(bid & 7) * 32], 1u);
        if ((r & 15u) == 15u) {                            // 16th arrival in group
            unsigned m = atomicAdd(&g_master, 1u);
            if ((m & 7u) == 7u)                            // 8th group done
                atomicExch(&g_gen, gen);
        }
        while ((int)(*(volatile unsigned*)&g_gen - gen) < 0) { }
        __threadfence();                                   // acquire
    }
    __syncthreads();
}

// ---------------- SGEMM v2: out[m,n] = sum_k X[m,k] * W[n,k] ---------------
// 128x128 tile, 8x8 micro-tile, BK=8, double-buffered SMEM.
// Numerics: per output, k-ascending FMA chain with kc=512 panel split,
// result = __fadd_rn(chain_lo, chain_hi)  — bitwise identical to round 10.
// EPI==1: sigmoid(acc + bias[n]) via 1/(1+expf(-x)).
template <int EPI>
__global__ __launch_bounds__(256, 1) void sgemm_nt(
    const float* __restrict__ X, const float* __restrict__ W,
    const float* __restrict__ bias, float* __restrict__ out,
    int M, int N, int K)
{
    __shared__ float Xs[2][8][132];
    __shared__ float Ws[2][8][132];

    const int n0 = blockIdx.x * 128;
    const int m0 = blockIdx.y * 128;
    const int tid = threadIdx.x;
    const int tx = tid & 15;            // 16 col-groups of 8
    const int ty = tid >> 4;            // 16 row-groups of 8

    const int lrow = tid >> 1;          // 0..127 (tile row to load)
    const int lkq  = (tid & 1) * 4;     // 0 or 4 (k quad within BK=8)

    const float* Xp = X + (size_t)(m0 + lrow) * K + lkq;
    const float* Wp = W + (size_t)(n0 + lrow) * K + lkq;

    float acc[8][8], accL[8][8];
#pragma unroll
    for (int i = 0; i < 8; i++)
#pragma unroll
        for (int j = 0; j < 8; j++) { acc[i][j] = 0.f; accL[i][j] = 0.f; }

    // preload tile 0
    float4 xv = *reinterpret_cast<const float4*>(Xp);
    float4 wv = *reinterpret_cast<const float4*>(Wp);
    Xs[0][lkq + 0][lrow] = xv.x; Xs[0][lkq + 1][lrow] = xv.y;
    Xs[0][lkq + 2][lrow] = xv.z; Xs[0][lkq + 3][lrow] = xv.w;
    Ws[0][lkq + 0][lrow] = wv.x; Ws[0][lkq + 1][lrow] = wv.y;
    Ws[0][lkq + 2][lrow] = wv.z; Ws[0][lkq + 3][lrow] = wv.w;
    __syncthreads();

    const int ntiles = K / 8;           // 128
#pragma unroll 1
    for (int it = 0; it < ntiles; it++) {
        const int buf = it & 1;
        if (it + 1 < ntiles) {          // prefetch next tile into registers
            xv = *reinterpret_cast<const float4*>(Xp + (it + 1) * 8);
            wv = *reinterpret_cast<const float4*>(Wp + (it + 1) * 8);
        }
#pragma unroll
        for (int k = 0; k < 8; k++) {   // k strictly ascending
            float a[8], b[8];
            *reinterpret_cast<float4*>(&a[0]) = *reinterpret_cast<const float4*>(&Xs[buf][k][ty * 8]);
            *reinterpret_cast<float4*>(&a[4]) = *reinterpret_cast<const float4*>(&Xs[buf][k][ty * 8 + 4]);
            *reinterpret_cast<float4*>(&b[0]) = *reinterpret_cast<const float4*>(&Ws[buf][k][tx * 8]);
            *reinterpret_cast<float4*>(&b[4]) = *reinterpret_cast<const float4*>(&Ws[buf][k][tx * 8 + 4]);
#pragma unroll
            for (int i = 0; i < 8; i++)
#pragma unroll
                for (int j = 0; j < 8; j++)
                    acc[i][j] = fmaf(a[i], b[j], acc[i][j]);
        }
        if ((it + 1) * 8 == 512) {      // kc=512 panel boundary
#pragma unroll
            for (int i = 0; i < 8; i++)
#pragma unroll
                for (int j = 0; j < 8; j++) { accL[i][j] = acc[i][j]; acc[i][j] = 0.f; }
        }
        if (it + 1 < ntiles) {
            const int nb = buf ^ 1;
            Xs[nb][lkq + 0][lrow] = xv.x; Xs[nb][lkq + 1][lrow] = xv.y;
            Xs[nb][lkq + 2][lrow] = xv.z; Xs[nb][lkq + 3][lrow] = xv.w;
            Ws[nb][lkq + 0][lrow] = wv.x; Ws[nb][lkq + 1][lrow] = wv.y;
            Ws[nb][lkq + 2][lrow] = wv.z; Ws[nb][lkq + 3][lrow] = wv.w;
        }
        __syncthreads();
    }

    float bv[8];
    if (EPI == 1) {
#pragma unroll
        for (int j = 0; j < 8; j++) bv[j] = bias[n0 + tx * 8 + j];
    }
#pragma unroll
    for (int i = 0; i < 8; i++) {
        float vals[8];
#pragma unroll
        for (int j = 0; j < 8; j++) {
            float v = __fadd_rn(accL[i][j], acc[i][j]);   // add(chain_lo, chain_hi)
            if (EPI == 1) v = 1.f / (1.f + expf(-(v + bv[j])));
            vals[j] = v;
        }
        float* po = out + (size_t)(m0 + ty * 8 + i) * N + n0 + tx * 8;
        float4 o0; o0.x = vals[0]; o0.y = vals[1]; o0.z = vals[2]; o0.w = vals[3];
        float4 o1; o1.x = vals[4]; o1.y = vals[5]; o1.z = vals[6]; o1.w = vals[7];
        *reinterpret_cast<float4*>(po)     = o0;
        *reinterpret_cast<float4*>(po + 4) = o1;
    }
}

// ---------------- persistent scan kernel (r10 numerics + prefetch) ---------
// grid = 128 CTAs x 256 threads. CTA owns 8 output channels h0..h0+7.
// thread: m = tid&127 (batch row), half = tid>>7 (k-split: 512 k each).
// dotA = add(chain(k<512), chain(k>=512)) — unchanged accumulation order.
__global__ __launch_bounds__(256) void scan_kernel(
    const float* __restrict__ state0, const float* __restrict__ A,
    const float* __restrict__ log_dt,
    const float* __restrict__ XB, const float* __restrict__ G,
    float* __restrict__ Sbuf, float* __restrict__ out_state)
{
    __shared__ float As[HH][8];      // A slice: As[k][j] = A[h0+j][k]
    __shared__ float Rs[BB][9];      // half-1 partial sums (pad 9)

    const int tid  = threadIdx.x;
    const int bid  = blockIdx.x;
    const int h0   = bid * 8;
    const int m    = tid & 127;
    const int half = tid >> 7;
    const int kbase = half * 512;

    for (int idx = tid; idx < 8 * HH; idx += 256) {
        int j = idx >> 10, k = idx & 1023;
        As[k][j] = A[(size_t)(h0 + j) * HH + k];
    }
    if (tid < BB) {
#pragma unroll
        for (int j = 0; j < 8; j++)
            g_sT[0][h0 + j][tid] = state0[(size_t)tid * HH + h0 + j];
    }

    float dt[8], sreg[8];
    if (half == 0) {
#pragma unroll
        for (int j = 0; j < 8; j++) {
            float d = expf(log_dt[h0 + j]);
            dt[j] = fminf(fmaxf(d, 0.001f), 0.1f);
            sreg[j] = state0[(size_t)m * HH + h0 + j];
        }
    }

    unsigned gen = *(volatile unsigned*)&g_gen;
    gsync(bid, gen);

    const float* sbase = &g_sT[0][0][0];

    for (int t = 0; t < SS; t++) {
        const int cur = t & 1;
        const int nxt = cur ^ 1;

        float4 xb0, xb1, gg0, gg1;
        size_t rowbase = ((size_t)m * SS + t) * HH + h0;
        if (half == 0) {
            xb0 = *reinterpret_cast<const float4*>(XB + rowbase);
            xb1 = *reinterpret_cast<const float4*>(XB + rowbase + 4);
            gg0 = *reinterpret_cast<const float4*>(G + rowbase);
            gg1 = *reinterpret_cast<const float4*>(G + rowbase + 4);
        }

        // single k-ascending chain over this thread's 512-k half,
        // software-pipelined: prefetch next 8 state values during FMAs.
        float acc[8];
#pragma unroll
        for (int j = 0; j < 8; j++) acc[j] = 0.f;

        const float* sp = sbase + (size_t)cur * HH * BB + (size_t)kbase * BB + m;
        float sv[8];
#pragma unroll
        for (int u = 0; u < 8; u++)
            sv[u] = __ldcg(sp + (size_t)u * BB);

#pragma unroll 1
        for (int kk = 0; kk < 512; kk += 8) {
            float nv[8];
            if (kk + 8 < 512) {
#pragma unroll
                for (int u = 0; u < 8; u++)
                    nv[u] = __ldcg(sp + (size_t)(kk + 8 + u) * BB);
            }
#pragma unroll
            for (int u = 0; u < 8; u++) {
                const float4 a0 = *reinterpret_cast<const float4*>(&As[kbase + kk + u][0]);
                const float4 a1 = *reinterpret_cast<const float4*>(&As[kbase + kk + u][4]);
                acc[0] = fmaf(sv[u], a0.x, acc[0]);
                acc[1] = fmaf(sv[u], a0.y, acc[1]);
                acc[2] = fmaf(sv[u], a0.z, acc[2]);
                acc[3] = fmaf(sv[u], a0.w, acc[3]);
                acc[4] = fmaf(sv[u], a1.x, acc[4]);
                acc[5] = fmaf(sv[u], a1.y, acc[5]);
                acc[6] = fmaf(sv[u], a1.z, acc[6]);
                acc[7] = fmaf(sv[u], a1.w, acc[7]);
            }
#pragma unroll
            for (int u = 0; u < 8; u++) sv[u] = nv[u];
        }

        if (half == 1) {
#pragma unroll
            for (int j = 0; j < 8; j++) Rs[m][j] = acc[j];
        }
        __syncthreads();

        if (half == 0) {
            float xb[8] = {xb0.x, xb0.y, xb0.z, xb0.w, xb1.x, xb1.y, xb1.z, xb1.w};
            float gv[8] = {gg0.x, gg0.y, gg0.z, gg0.w, gg1.x, gg1.y, gg1.z, gg1.w};
            float sn[8];
#pragma unroll
            for (int j = 0; j < 8; j++) {
                float dstate = acc[j] + Rs[m][j] + xb[j];   // (lo+hi)+xb
                float sc = dstate * dt[j];
                if (fabsf(sc) <= 0.1f) sc = 0.f;
                float v = sreg[j] + sc * gv[j];             // default contraction (as r10)
                sreg[j] = v;
                sn[j] = v;
                g_sT[nxt][h0 + j][m] = v;
            }
            float4 o0; o0.x = sn[0]; o0.y = sn[1]; o0.z = sn[2]; o0.w = sn[3];
            float4 o1; o1.x = sn[4]; o1.y = sn[5]; o1.z = sn[6]; o1.w = sn[7];
            *reinterpret_cast<float4*>(Sbuf + rowbase)     = o0;
            *reinterpret_cast<float4*>(Sbuf + rowbase + 4) = o1;
            if (t == SS - 1 && out_state != nullptr) {
#pragma unroll
                for (int j = 0; j < 8; j++)
                    out_state[(size_t)m * HH + h0 + j] = sn[j];
            }
        }

        gsync(bid, gen);
    }
}

// ---------------- launch ----------------------------------------------------
extern "C" void kernel_launch(void* const* d_in, const int* in_sizes, int n_in,
                              void* d_out, int out_size) {
    const float* x      = (const float*)d_in[0];
    const float* state  = (const float*)d_in[1];
    const float* A      = (const float*)d_in[2];
    const float* Bm     = (const float*)d_in[3];
    const float* C      = (const float*)d_in[4];
    const float* log_dt = (const float*)d_in[5];
    const float* Wg     = (const float*)d_in[6];
    const float* bg     = (const float*)d_in[7];

    float* ys = (float*)d_out;
    const size_t ys_elems = (size_t)BB * SS * HH;
    float* out_state = nullptr;
    if ((size_t)out_size >= ys_elems + (size_t)BB * HH)
        out_state = ys + ys_elems;

    float *pXB = nullptr, *pG = nullptr, *pS = nullptr;
    cudaGetSymbolAddress((void**)&pXB, g_XB);
    cudaGetSymbolAddress((void**)&pG,  g_G);
    cudaGetSymbolAddress((void**)&pS,  g_Sbuf);

    const int M = BB * SS;            // 65536
    dim3 grid(HH / 128, M / 128);     // (8, 512), n fastest

    // off-critical-path GEMMs (kc=512 blocked chains, bitwise == round 10)
    sgemm_nt<0><<<grid, 256>>>(x, Bm, nullptr, pXB, M, HH, HH);
    sgemm_nt<1><<<grid, 256>>>(x, Wg, bg,      pG,  M, HH, HH);

    // sequential scan (persistent, 128 CTAs), 2x512 chains
    scan_kernel<<<BB, 256>>>(state, A, log_dt, pXB, pG, pS, out_state);

    // y = Sbuf @ C^T (kc=512 blocked chains)
    sgemm_nt<0><<<grid, 256>>>(pS, C, nullptr, ys, M, HH, HH);
}